// round 5
// baseline (speedup 1.0000x reference)
#include <cuda_runtime.h>
#include <cuda_bf16.h>
#include <cstdint>

#define N_NODES 100000
#define N_EDGES 600000
#define DD 128
#define TWD 768
#define RR 2

// ---------------------------------------------------------------------------
// Scratch (device globals — no allocation allowed)
// ---------------------------------------------------------------------------
__device__ float g_bufA[(size_t)N_NODES * DD];          // 51.2 MB
__device__ float g_bufB[(size_t)N_NODES * DD];          // 51.2 MB
__device__ float g_agg[(size_t)N_NODES * RR * DD];      // 102.4 MB
__device__ float g_cnt[(size_t)N_NODES * RR];           // 0.8 MB

// Weight fragment blobs (bf16): per stage, hi plane then lo plane.
// Plane layout: uint2 per (k16-step s, n8-tile j, lane): idx = ((s*16+j)*32+lane)
// offsets (bf16 elems): tweet 0 (768*128*2), Win 196608 (+32768),
// combine 229376 (+98304), Wout1 327680 (+32768). total 360448.
#define BLOB_TWEET 0
#define BLOB_WIN   196608
#define BLOB_COMB  229376
#define BLOB_WOUT1 327680
#define BLOB_TOTAL 360448
__device__ __nv_bfloat16 g_wblob[BLOB_TOTAL];

// ---------------------------------------------------------------------------
// MMA helpers (plain PTX: valid on sm_103 virtual target, unlike tcgen05)
// ---------------------------------------------------------------------------
__device__ __forceinline__ void mma16816(float* c, const uint32_t* a, uint2 b) {
    asm volatile(
        "mma.sync.aligned.m16n8k16.row.col.f32.bf16.bf16.f32 "
        "{%0,%1,%2,%3}, {%4,%5,%6,%7}, {%8,%9}, {%0,%1,%2,%3};"
        : "+f"(c[0]), "+f"(c[1]), "+f"(c[2]), "+f"(c[3])
        : "r"(a[0]), "r"(a[1]), "r"(a[2]), "r"(a[3]), "r"(b.x), "r"(b.y));
}

__device__ __forceinline__ void ldmat4(uint32_t* d, uint32_t addr) {
    asm volatile("ldmatrix.sync.aligned.m8n8.x4.shared.b16 {%0,%1,%2,%3}, [%4];"
                 : "=r"(d[0]), "=r"(d[1]), "=r"(d[2]), "=r"(d[3]) : "r"(addr));
}

// fragment index (bf16 elems within a plane) for element (k, n)
__device__ __forceinline__ int frag_idx(int k, int n) {
    int s = k >> 4, j = n >> 3;
    int lane = (n & 7) * 4 + ((k & 7) >> 1);
    return ((((s * 16 + j) * 32 + lane) * 2 + ((k >> 3) & 1)) << 1) + (k & 1);
}

// ---------------------------------------------------------------------------
// Weight prep: fp32 W[K,128] -> bf16 hi/lo fragment planes
// ---------------------------------------------------------------------------
__global__ void convert_weights(
    const float* __restrict__ Wt, const float* __restrict__ Wi,
    const float* __restrict__ root, const float* __restrict__ rw,
    const float* __restrict__ Wo1, __nv_bfloat16* __restrict__ blob)
{
    int i = blockIdx.x * blockDim.x + threadIdx.x;
    if (i >= 1408 * 128) return;
    int n = i & 127;
    int kk = i >> 7;
    float w; int k, base, Kphys;
    if (kk < 768)       { k = kk;        base = BLOB_TWEET; Kphys = 768; w = Wt[k * 128 + n]; }
    else if (kk < 896)  { k = kk - 768;  base = BLOB_WIN;   Kphys = 128; w = Wi[k * 128 + n]; }
    else if (kk < 1280) { k = kk - 896;  base = BLOB_COMB;  Kphys = 384;
                          w = (k < 128) ? root[k * 128 + n] : rw[(size_t)(k - 128) * 128 + n]; }
    else                { k = kk - 1280; base = BLOB_WOUT1; Kphys = 128; w = Wo1[k * 128 + n]; }

    __nv_bfloat16 h = __float2bfloat16_rn(w);
    __nv_bfloat16 l = __float2bfloat16_rn(w - __bfloat162float(h));
    int fi = frag_idx(k, n);
    blob[base + fi] = h;
    blob[base + Kphys * 128 + fi] = l;
}

// ---------------------------------------------------------------------------
// HMMA GEMM: C[M,128] = act( concat(A1[,:K1], A2_scaled)[M,Kphys] @ W + bias )
// A2 rows scaled by 1/max(cnt[row*2 + rel],1) (normalize folded in).
// 3-term bf16 split: C = Ah*Bh + Al*Bh + Ah*Bl.
// ---------------------------------------------------------------------------
__global__ __launch_bounds__(256, 1) void mma_gemm(
    const float* __restrict__ A1, int K1, int s1,
    const float* __restrict__ A2, int s2, const float* __restrict__ cnt,
    const __nv_bfloat16* __restrict__ Wblob, int Kphys,
    const float* __restrict__ bias, float* __restrict__ C,
    int M, int act)
{
    __shared__ __nv_bfloat16 Ah[128][40];
    __shared__ __nv_bfloat16 Al[128][40];

    const int tid = threadIdx.x;
    const int wid = tid >> 5;
    const int lane = tid & 31;
    const int wr = wid & 3;           // 32-row group
    const int wc = wid >> 2;          // 64-col group
    const int row0 = blockIdx.x * 128;

    const uint2* __restrict__ BH = (const uint2*)Wblob;
    const uint2* __restrict__ BL = (const uint2*)(Wblob + (size_t)Kphys * 128);

    float acc[2][8][4];
#pragma unroll
    for (int mt = 0; mt < 2; mt++)
#pragma unroll
        for (int j = 0; j < 8; j++)
#pragma unroll
            for (int q = 0; q < 4; q++) acc[mt][j][q] = 0.f;

    // A-load assignment: 2 threads per row, 16 k each
    const int lrow = tid >> 1;
    const int lk = (tid & 1) * 16;
    const int gr = row0 + lrow;
    const bool av = gr < M;
    uint32_t ah_base = (uint32_t)__cvta_generic_to_shared(&Ah[0][0]);
    uint32_t al_base = (uint32_t)__cvta_generic_to_shared(&Al[0][0]);

    const int nChunks = Kphys >> 5;
    for (int c = 0; c < nChunks; c++) {
        // ---- load A fp32 [128 x 32], split hi/lo into SMEM ----
        {
            int kp = (c << 5) + lk;
            float4 f0 = make_float4(0, 0, 0, 0), f1 = f0, f2 = f0, f3 = f0;
            if (av) {
                const float* src;
                float sc = 1.f;
                if (kp < K1) {
                    src = A1 + (size_t)gr * s1 + kp;
                } else {
                    int ka = kp - K1;
                    int rel = ka >> 7;
                    sc = 1.f / fmaxf(__ldg(&cnt[gr * 2 + rel]), 1.f);
                    src = A2 + (size_t)gr * s2 + ka;
                }
                f0 = *(const float4*)(src + 0);
                f1 = *(const float4*)(src + 4);
                f2 = *(const float4*)(src + 8);
                f3 = *(const float4*)(src + 12);
                f0.x *= sc; f0.y *= sc; f0.z *= sc; f0.w *= sc;
                f1.x *= sc; f1.y *= sc; f1.z *= sc; f1.w *= sc;
                f2.x *= sc; f2.y *= sc; f2.z *= sc; f2.w *= sc;
                f3.x *= sc; f3.y *= sc; f3.z *= sc; f3.w *= sc;
            }
            float f[16] = {f0.x, f0.y, f0.z, f0.w, f1.x, f1.y, f1.z, f1.w,
                           f2.x, f2.y, f2.z, f2.w, f3.x, f3.y, f3.z, f3.w};
            uint32_t* dh = (uint32_t*)&Ah[lrow][lk];
            uint32_t* dl = (uint32_t*)&Al[lrow][lk];
#pragma unroll
            for (int i = 0; i < 8; i++) {
                __nv_bfloat162 h, l;
                h.x = __float2bfloat16_rn(f[2 * i]);
                h.y = __float2bfloat16_rn(f[2 * i + 1]);
                l.x = __float2bfloat16_rn(f[2 * i] - __bfloat162float(h.x));
                l.y = __float2bfloat16_rn(f[2 * i + 1] - __bfloat162float(h.y));
                dh[i] = *(uint32_t*)&h;
                dl[i] = *(uint32_t*)&l;
            }
        }
        __syncthreads();

        // ---- MMA over the 2 k16-steps of this chunk ----
#pragma unroll
        for (int s = 0; s < 2; s++) {
            uint32_t ahf[2][4], alf[2][4];
            int mrow = lane & 15;
            int mk = (s << 4) + ((lane >> 4) << 3);
#pragma unroll
            for (int mt = 0; mt < 2; mt++) {
                uint32_t off = (uint32_t)(((wr * 32 + mt * 16 + mrow) * 40 + mk) * 2);
                ldmat4(ahf[mt], ah_base + off);
                ldmat4(alf[mt], al_base + off);
            }
            int sg = c * 2 + s;
            const uint2* bh = BH + ((size_t)sg * 16 + wc * 8) * 32 + lane;
            const uint2* bl = BL + ((size_t)sg * 16 + wc * 8) * 32 + lane;
#pragma unroll
            for (int j = 0; j < 8; j++) {
                uint2 vh = __ldg(&bh[j * 32]);
                uint2 vl = __ldg(&bl[j * 32]);
#pragma unroll
                for (int mt = 0; mt < 2; mt++) {
                    mma16816(acc[mt][j], ahf[mt], vh);
                    mma16816(acc[mt][j], alf[mt], vh);
                    mma16816(acc[mt][j], ahf[mt], vl);
                }
            }
        }
        __syncthreads();
    }

    // ---- epilogue: bias + act + store ----
#pragma unroll
    for (int mt = 0; mt < 2; mt++) {
#pragma unroll
        for (int j = 0; j < 8; j++) {
            int col = wc * 64 + j * 8 + (lane & 3) * 2;
            int r0 = row0 + wr * 32 + mt * 16 + (lane >> 2);
            float b0 = __ldg(&bias[col]), b1 = __ldg(&bias[col + 1]);
            float v0 = acc[mt][j][0] + b0, v1 = acc[mt][j][1] + b1;
            float v2 = acc[mt][j][2] + b0, v3 = acc[mt][j][3] + b1;
            if (act) {
                v0 = (v0 > 0.f) ? v0 : 0.01f * v0;
                v1 = (v1 > 0.f) ? v1 : 0.01f * v1;
                v2 = (v2 > 0.f) ? v2 : 0.01f * v2;
                v3 = (v3 > 0.f) ? v3 : 0.01f * v3;
            }
            if (r0 < M)     *(float2*)&C[(size_t)r0 * 128 + col]       = make_float2(v0, v1);
            if (r0 + 8 < M) *(float2*)&C[(size_t)(r0 + 8) * 128 + col] = make_float2(v2, v3);
        }
    }
}

// ---------------------------------------------------------------------------
// Edge path
// ---------------------------------------------------------------------------
__global__ void zero_kernel(float* __restrict__ agg, float* __restrict__ cnt)
{
    size_t i = (size_t)blockIdx.x * blockDim.x + threadIdx.x;
    const size_t tot = (size_t)N_NODES * RR * DD;
    if (i < tot) agg[i] = 0.f;
    if (i < (size_t)N_NODES * RR) cnt[i] = 0.f;
}

__global__ __launch_bounds__(128) void edge_agg(
    const int* __restrict__ src, const int* __restrict__ dst,
    const int* __restrict__ et, const float* __restrict__ x,
    float* __restrict__ agg, float* __restrict__ cnt)
{
    const int t = threadIdx.x;
    const int e0 = blockIdx.x * 4;
#pragma unroll
    for (int i = 0; i < 4; i++) {
        int e = e0 + i;
        if (e >= N_EDGES) return;
        int s = __ldg(&src[e]);
        int d = __ldg(&dst[e]);
        int r = __ldg(&et[e]);
        float v = __ldg(&x[(size_t)s * 128 + t]);
        atomicAdd(&agg[((size_t)d * RR + r) * 128 + t], v);
        if (t == 0) atomicAdd(&cnt[(size_t)d * RR + r], 1.0f);
    }
}

__global__ __launch_bounds__(128) void out2_kernel(
    const float* __restrict__ x, const float* __restrict__ W,
    const float* __restrict__ b, float* __restrict__ out, int M)
{
    __shared__ float Ws[256];
    int tid = threadIdx.x;
    Ws[tid] = W[tid];
    Ws[tid + 128] = W[tid + 128];
    __syncthreads();

    int warp = tid >> 5, lane = tid & 31;
    int n = blockIdx.x * 4 + warp;
    if (n >= M) return;

    float4 v = *(const float4*)&x[(size_t)n * 128 + lane * 4];
    int k = lane * 4;
    float d0 = v.x * Ws[(k + 0) * 2] + v.y * Ws[(k + 1) * 2] +
               v.z * Ws[(k + 2) * 2] + v.w * Ws[(k + 3) * 2];
    float d1 = v.x * Ws[(k + 0) * 2 + 1] + v.y * Ws[(k + 1) * 2 + 1] +
               v.z * Ws[(k + 2) * 2 + 1] + v.w * Ws[(k + 3) * 2 + 1];
#pragma unroll
    for (int off = 16; off > 0; off >>= 1) {
        d0 += __shfl_down_sync(0xFFFFFFFFu, d0, off);
        d1 += __shfl_down_sync(0xFFFFFFFFu, d1, off);
    }
    if (lane == 0) {
        out[(size_t)n * 2 + 0] = d0 + b[0];
        out[(size_t)n * 2 + 1] = d1 + b[1];
    }
}

// ---------------------------------------------------------------------------
extern "C" void kernel_launch(void* const* d_in, const int* in_sizes, int n_in,
                              void* d_out, int out_size)
{
    const float* tweet     = (const float*)d_in[1];
    const int*   ei        = (const int*)d_in[4];
    const int*   etype     = (const int*)d_in[5];
    const float* W_tweet   = (const float*)d_in[6];
    const float* b_tweet   = (const float*)d_in[7];
    const float* W_in      = (const float*)d_in[8];
    const float* b_in      = (const float*)d_in[9];
    const float* rgcn_w    = (const float*)d_in[10];
    const float* rgcn_root = (const float*)d_in[11];
    const float* rgcn_b    = (const float*)d_in[12];
    const float* W_out1    = (const float*)d_in[13];
    const float* b_out1    = (const float*)d_in[14];
    const float* W_out2    = (const float*)d_in[15];
    const float* b_out2    = (const float*)d_in[16];
    float* out = (float*)d_out;

    float *bufA, *bufB, *agg, *cnt;
    __nv_bfloat16* blob;
    cudaGetSymbolAddress((void**)&bufA, g_bufA);
    cudaGetSymbolAddress((void**)&bufB, g_bufB);
    cudaGetSymbolAddress((void**)&agg, g_agg);
    cudaGetSymbolAddress((void**)&cnt, g_cnt);
    cudaGetSymbolAddress((void**)&blob, g_wblob);

    const int M = N_NODES;
    const int gemm_blocks = (M + 127) / 128;
    const int zero_blocks = (int)(((size_t)N_NODES * RR * DD + 255) / 256);
    const int edge_blocks = (N_EDGES + 3) / 4;

    const int* src = ei;
    const int* dst = ei + N_EDGES;

    convert_weights<<<(1408 * 128 + 255) / 256, 256>>>(W_tweet, W_in, rgcn_root, rgcn_w, W_out1, blob);

    // t = lrelu(tweet @ W_tweet + b)
    mma_gemm<<<gemm_blocks, 256>>>(tweet, TWD, TWD, nullptr, 0, nullptr,
                                   blob + BLOB_TWEET, TWD, b_tweet, bufA, M, 1);
    // x = lrelu(t @ W_in + b)
    mma_gemm<<<gemm_blocks, 256>>>(bufA, DD, DD, nullptr, 0, nullptr,
                                   blob + BLOB_WIN, DD, b_in, bufB, M, 1);

    // conv1: bufB -> bufA
    zero_kernel<<<zero_blocks, 256>>>(agg, cnt);
    edge_agg<<<edge_blocks, 128>>>(src, dst, etype, bufB, agg, cnt);
    mma_gemm<<<gemm_blocks, 256>>>(bufB, DD, DD, agg, RR * DD, cnt,
                                   blob + BLOB_COMB, 3 * DD, rgcn_b, bufA, M, 0);

    // conv2: bufA -> bufB
    zero_kernel<<<zero_blocks, 256>>>(agg, cnt);
    edge_agg<<<edge_blocks, 128>>>(src, dst, etype, bufA, agg, cnt);
    mma_gemm<<<gemm_blocks, 256>>>(bufA, DD, DD, agg, RR * DD, cnt,
                                   blob + BLOB_COMB, 3 * DD, rgcn_b, bufB, M, 0);

    // out1 = lrelu(x @ W_out1 + b)
    mma_gemm<<<gemm_blocks, 256>>>(bufB, DD, DD, nullptr, 0, nullptr,
                                   blob + BLOB_WOUT1, DD, b_out1, bufA, M, 1);
    // out = out1 @ W_out2 + b2
    out2_kernel<<<(M + 3) / 4, 128>>>(bufA, W_out2, b_out2, out, M);
}

// round 6
// speedup vs baseline: 1.1004x; 1.1004x over previous
#include <cuda_runtime.h>
#include <cuda_bf16.h>
#include <cstdint>

#define N_NODES 100000
#define N_EDGES 600000
#define DD 128
#define TWD 768
#define RR 2

// ---------------------------------------------------------------------------
// Scratch (device globals — no allocation allowed)
// ---------------------------------------------------------------------------
__device__ float g_bufA[(size_t)N_NODES * DD];          // 51.2 MB
__device__ float g_bufB[(size_t)N_NODES * DD];          // 51.2 MB
__device__ float g_agg[(size_t)N_NODES * RR * DD];      // 102.4 MB
__device__ float g_cnt[(size_t)N_NODES * RR];           // 0.8 MB

// Weight fragment blobs (bf16): per stage, hi plane then lo plane.
// Plane layout: uint2 per (k16-step s, n8-tile j, lane): idx = ((s*16+j)*32+lane)
#define BLOB_TWEET 0
#define BLOB_WIN   196608
#define BLOB_COMB  229376
#define BLOB_WOUT1 327680
#define BLOB_TOTAL 360448
__device__ __nv_bfloat16 g_wblob[BLOB_TOTAL];

// ---------------------------------------------------------------------------
// MMA helpers (plain PTX: valid on sm_103 virtual target)
// ---------------------------------------------------------------------------
__device__ __forceinline__ void mma16816(float* c, const uint32_t* a, uint2 b) {
    asm volatile(
        "mma.sync.aligned.m16n8k16.row.col.f32.bf16.bf16.f32 "
        "{%0,%1,%2,%3}, {%4,%5,%6,%7}, {%8,%9}, {%0,%1,%2,%3};"
        : "+f"(c[0]), "+f"(c[1]), "+f"(c[2]), "+f"(c[3])
        : "r"(a[0]), "r"(a[1]), "r"(a[2]), "r"(a[3]), "r"(b.x), "r"(b.y));
}

__device__ __forceinline__ void ldmat4(uint32_t* d, uint32_t addr) {
    asm volatile("ldmatrix.sync.aligned.m8n8.x4.shared.b16 {%0,%1,%2,%3}, [%4];"
                 : "=r"(d[0]), "=r"(d[1]), "=r"(d[2]), "=r"(d[3]) : "r"(addr));
}

// fragment index (bf16 elems within a plane) for element (k, n)
__device__ __forceinline__ int frag_idx(int k, int n) {
    int s = k >> 4, j = n >> 3;
    int lane = (n & 7) * 4 + ((k & 7) >> 1);
    return ((((s * 16 + j) * 32 + lane) * 2 + ((k >> 3) & 1)) << 1) + (k & 1);
}

// ---------------------------------------------------------------------------
// Weight prep: fp32 W[K,128] -> bf16 hi/lo fragment planes
// ---------------------------------------------------------------------------
__global__ void convert_weights(
    const float* __restrict__ Wt, const float* __restrict__ Wi,
    const float* __restrict__ root, const float* __restrict__ rw,
    const float* __restrict__ Wo1, __nv_bfloat16* __restrict__ blob)
{
    int i = blockIdx.x * blockDim.x + threadIdx.x;
    if (i >= 1408 * 128) return;
    int n = i & 127;
    int kk = i >> 7;
    float w; int k, base, Kphys;
    if (kk < 768)       { k = kk;        base = BLOB_TWEET; Kphys = 768; w = Wt[k * 128 + n]; }
    else if (kk < 896)  { k = kk - 768;  base = BLOB_WIN;   Kphys = 128; w = Wi[k * 128 + n]; }
    else if (kk < 1280) { k = kk - 896;  base = BLOB_COMB;  Kphys = 384;
                          w = (k < 128) ? root[k * 128 + n] : rw[(size_t)(k - 128) * 128 + n]; }
    else                { k = kk - 1280; base = BLOB_WOUT1; Kphys = 128; w = Wo1[k * 128 + n]; }

    __nv_bfloat16 h = __float2bfloat16_rn(w);
    __nv_bfloat16 l = __float2bfloat16_rn(w - __bfloat162float(h));
    int fi = frag_idx(k, n);
    blob[base + fi] = h;
    blob[base + Kphys * 128 + fi] = l;
}

// ---------------------------------------------------------------------------
// HMMA GEMM, software-pipelined:
// C[M,128] = act( concat(A1[,:K1], A2_scaled)[M,Kphys] @ W + bias )
// double-buffered A SMEM; B fragments prefetched to registers per k16-step.
// 3-term bf16 split: C = Ah*Bh + Al*Bh + Ah*Bl.
// ---------------------------------------------------------------------------
__global__ __launch_bounds__(256, 1) void mma_gemm(
    const float* __restrict__ A1, int K1, int s1,
    const float* __restrict__ A2, int s2, const float* __restrict__ cnt,
    const __nv_bfloat16* __restrict__ Wblob, int Kphys,
    const float* __restrict__ bias, float* __restrict__ C,
    int M, int act)
{
    __shared__ __nv_bfloat16 Ah[2][128][40];
    __shared__ __nv_bfloat16 Al[2][128][40];

    const int tid = threadIdx.x;
    const int wid = tid >> 5;
    const int lane = tid & 31;
    const int wr = wid & 3;           // 32-row group
    const int wc = wid >> 2;          // 64-col group
    const int row0 = blockIdx.x * 128;

    const uint2* __restrict__ BH = (const uint2*)Wblob;
    const uint2* __restrict__ BL = (const uint2*)(Wblob + (size_t)Kphys * 128);

    float acc[2][8][4];
#pragma unroll
    for (int mt = 0; mt < 2; mt++)
#pragma unroll
        for (int j = 0; j < 8; j++)
#pragma unroll
            for (int q = 0; q < 4; q++) acc[mt][j][q] = 0.f;

    // A-load assignment: 2 threads per row, 16 k each
    const int lrow = tid >> 1;
    const int lk = (tid & 1) * 16;
    const int gr = row0 + lrow;
    const bool av = gr < M;
    const uint32_t ah_base = (uint32_t)__cvta_generic_to_shared(&Ah[0][0][0]);
    const uint32_t al_base = (uint32_t)__cvta_generic_to_shared(&Al[0][0][0]);
    const uint32_t bufstride = 128 * 40 * 2;

    float f[16];

    // ldg chunk c into f[]
    auto ldgA = [&](int c) {
        int kp = (c << 5) + lk;
#pragma unroll
        for (int i = 0; i < 16; i++) f[i] = 0.f;
        if (av) {
            const float* src;
            float sc = 1.f;
            if (kp < K1) {
                src = A1 + (size_t)gr * s1 + kp;
            } else {
                int ka = kp - K1;
                int rel = ka >> 7;
                sc = 1.f / fmaxf(__ldg(&cnt[gr * 2 + rel]), 1.f);
                src = A2 + (size_t)gr * s2 + ka;
            }
            float4 f0 = *(const float4*)(src + 0);
            float4 f1 = *(const float4*)(src + 4);
            float4 f2 = *(const float4*)(src + 8);
            float4 f3 = *(const float4*)(src + 12);
            f[0] = f0.x * sc; f[1] = f0.y * sc; f[2] = f0.z * sc; f[3] = f0.w * sc;
            f[4] = f1.x * sc; f[5] = f1.y * sc; f[6] = f1.z * sc; f[7] = f1.w * sc;
            f[8] = f2.x * sc; f[9] = f2.y * sc; f[10] = f2.z * sc; f[11] = f2.w * sc;
            f[12] = f3.x * sc; f[13] = f3.y * sc; f[14] = f3.z * sc; f[15] = f3.w * sc;
        }
    };
    // convert f[] and store into SMEM buffer b
    auto stsA = [&](int b) {
        uint32_t* dh = (uint32_t*)&Ah[b][lrow][lk];
        uint32_t* dl = (uint32_t*)&Al[b][lrow][lk];
#pragma unroll
        for (int i = 0; i < 8; i++) {
            __nv_bfloat162 h, l;
            h.x = __float2bfloat16_rn(f[2 * i]);
            h.y = __float2bfloat16_rn(f[2 * i + 1]);
            l.x = __float2bfloat16_rn(f[2 * i] - __bfloat162float(h.x));
            l.y = __float2bfloat16_rn(f[2 * i + 1] - __bfloat162float(h.y));
            dh[i] = *(uint32_t*)&h;
            dl[i] = *(uint32_t*)&l;
        }
    };

    const int nChunks = Kphys >> 5;
    ldgA(0);
    stsA(0);
    __syncthreads();

    for (int c = 0; c < nChunks; c++) {
        const int cur = c & 1;
        const bool more = (c + 1) < nChunks;
        if (more) ldgA(c + 1);    // LDGs in flight during the MMAs below

        // ---- MMA over the 2 k16-steps of this chunk ----
#pragma unroll
        for (int s = 0; s < 2; s++) {
            const int sg = c * 2 + s;
            const uint2* bh = BH + ((size_t)sg * 16 + wc * 8) * 32 + lane;
            const uint2* bl = BL + ((size_t)sg * 16 + wc * 8) * 32 + lane;
            uint2 vh[8], vl[8];
#pragma unroll
            for (int j = 0; j < 8; j++) { vh[j] = __ldg(&bh[j * 32]); vl[j] = __ldg(&bl[j * 32]); }

            uint32_t ahf[2][4], alf[2][4];
            const int mrow = lane & 15;
            const int mk = (s << 4) + ((lane >> 4) << 3);
#pragma unroll
            for (int mt = 0; mt < 2; mt++) {
                uint32_t off = cur * bufstride + (uint32_t)(((wr * 32 + mt * 16 + mrow) * 40 + mk) * 2);
                ldmat4(ahf[mt], ah_base + off);
                ldmat4(alf[mt], al_base + off);
            }
#pragma unroll
            for (int j = 0; j < 8; j++) {
#pragma unroll
                for (int mt = 0; mt < 2; mt++) {
                    mma16816(acc[mt][j], ahf[mt], vh[j]);
                    mma16816(acc[mt][j], alf[mt], vh[j]);
                    mma16816(acc[mt][j], ahf[mt], vl[j]);
                }
            }
        }

        if (more) stsA(cur ^ 1);
        __syncthreads();
    }

    // ---- epilogue: bias + act + store ----
#pragma unroll
    for (int mt = 0; mt < 2; mt++) {
#pragma unroll
        for (int j = 0; j < 8; j++) {
            int col = wc * 64 + j * 8 + (lane & 3) * 2;
            int r0 = row0 + wr * 32 + mt * 16 + (lane >> 2);
            float b0 = __ldg(&bias[col]), b1 = __ldg(&bias[col + 1]);
            float v0 = acc[mt][j][0] + b0, v1 = acc[mt][j][1] + b1;
            float v2 = acc[mt][j][2] + b0, v3 = acc[mt][j][3] + b1;
            if (act) {
                v0 = (v0 > 0.f) ? v0 : 0.01f * v0;
                v1 = (v1 > 0.f) ? v1 : 0.01f * v1;
                v2 = (v2 > 0.f) ? v2 : 0.01f * v2;
                v3 = (v3 > 0.f) ? v3 : 0.01f * v3;
            }
            if (r0 < M)     *(float2*)&C[(size_t)r0 * 128 + col]       = make_float2(v0, v1);
            if (r0 + 8 < M) *(float2*)&C[(size_t)(r0 + 8) * 128 + col] = make_float2(v2, v3);
        }
    }
}

// ---------------------------------------------------------------------------
// Edge path
// ---------------------------------------------------------------------------
__global__ void zero_kernel(float4* __restrict__ agg4, float4* __restrict__ cnt4)
{
    const int stride = gridDim.x * blockDim.x;
    const int tot_agg = N_NODES * RR * DD / 4;
    const int tot_cnt = N_NODES * RR / 4;
    const float4 z = make_float4(0.f, 0.f, 0.f, 0.f);
    for (int i = blockIdx.x * blockDim.x + threadIdx.x; i < tot_agg; i += stride)
        agg4[i] = z;
    for (int i = blockIdx.x * blockDim.x + threadIdx.x; i < tot_cnt; i += stride)
        cnt4[i] = z;
}

__global__ __launch_bounds__(128) void edge_agg(
    const int* __restrict__ src, const int* __restrict__ dst,
    const int* __restrict__ et, const float* __restrict__ x,
    float* __restrict__ agg, float* __restrict__ cnt)
{
    const int t = threadIdx.x;
    const int e0 = blockIdx.x * 4;
#pragma unroll
    for (int i = 0; i < 4; i++) {
        int e = e0 + i;
        if (e >= N_EDGES) return;
        int s = __ldg(&src[e]);
        int d = __ldg(&dst[e]);
        int r = __ldg(&et[e]);
        float v = __ldg(&x[(size_t)s * 128 + t]);
        atomicAdd(&agg[((size_t)d * RR + r) * 128 + t], v);
        if (t == 0) atomicAdd(&cnt[(size_t)d * RR + r], 1.0f);
    }
}

__global__ __launch_bounds__(128) void out2_kernel(
    const float* __restrict__ x, const float* __restrict__ W,
    const float* __restrict__ b, float* __restrict__ out, int M)
{
    __shared__ float Ws[256];
    int tid = threadIdx.x;
    Ws[tid] = W[tid];
    Ws[tid + 128] = W[tid + 128];
    __syncthreads();

    int warp = tid >> 5, lane = tid & 31;
    int n = blockIdx.x * 4 + warp;
    if (n >= M) return;

    float4 v = *(const float4*)&x[(size_t)n * 128 + lane * 4];
    int k = lane * 4;
    float d0 = v.x * Ws[(k + 0) * 2] + v.y * Ws[(k + 1) * 2] +
               v.z * Ws[(k + 2) * 2] + v.w * Ws[(k + 3) * 2];
    float d1 = v.x * Ws[(k + 0) * 2 + 1] + v.y * Ws[(k + 1) * 2 + 1] +
               v.z * Ws[(k + 2) * 2 + 1] + v.w * Ws[(k + 3) * 2 + 1];
#pragma unroll
    for (int off = 16; off > 0; off >>= 1) {
        d0 += __shfl_down_sync(0xFFFFFFFFu, d0, off);
        d1 += __shfl_down_sync(0xFFFFFFFFu, d1, off);
    }
    if (lane == 0) {
        out[(size_t)n * 2 + 0] = d0 + b[0];
        out[(size_t)n * 2 + 1] = d1 + b[1];
    }
}

// ---------------------------------------------------------------------------
extern "C" void kernel_launch(void* const* d_in, const int* in_sizes, int n_in,
                              void* d_out, int out_size)
{
    const float* tweet     = (const float*)d_in[1];
    const int*   ei        = (const int*)d_in[4];
    const int*   etype     = (const int*)d_in[5];
    const float* W_tweet   = (const float*)d_in[6];
    const float* b_tweet   = (const float*)d_in[7];
    const float* W_in      = (const float*)d_in[8];
    const float* b_in      = (const float*)d_in[9];
    const float* rgcn_w    = (const float*)d_in[10];
    const float* rgcn_root = (const float*)d_in[11];
    const float* rgcn_b    = (const float*)d_in[12];
    const float* W_out1    = (const float*)d_in[13];
    const float* b_out1    = (const float*)d_in[14];
    const float* W_out2    = (const float*)d_in[15];
    const float* b_out2    = (const float*)d_in[16];
    float* out = (float*)d_out;

    float *bufA, *bufB, *agg, *cnt;
    __nv_bfloat16* blob;
    cudaGetSymbolAddress((void**)&bufA, g_bufA);
    cudaGetSymbolAddress((void**)&bufB, g_bufB);
    cudaGetSymbolAddress((void**)&agg, g_agg);
    cudaGetSymbolAddress((void**)&cnt, g_cnt);
    cudaGetSymbolAddress((void**)&blob, g_wblob);

    const int M = N_NODES;
    const int gemm_blocks = (M + 127) / 128;
    const int edge_blocks = (N_EDGES + 3) / 4;

    const int* src = ei;
    const int* dst = ei + N_EDGES;

    convert_weights<<<(1408 * 128 + 255) / 256, 256>>>(W_tweet, W_in, rgcn_root, rgcn_w, W_out1, blob);

    // t = lrelu(tweet @ W_tweet + b)
    mma_gemm<<<gemm_blocks, 256>>>(tweet, TWD, TWD, nullptr, 0, nullptr,
                                   blob + BLOB_TWEET, TWD, b_tweet, bufA, M, 1);
    // x = lrelu(t @ W_in + b)
    mma_gemm<<<gemm_blocks, 256>>>(bufA, DD, DD, nullptr, 0, nullptr,
                                   blob + BLOB_WIN, DD, b_in, bufB, M, 1);

    // conv1: bufB -> bufA
    zero_kernel<<<1184, 256>>>((float4*)agg, (float4*)cnt);
    edge_agg<<<edge_blocks, 128>>>(src, dst, etype, bufB, agg, cnt);
    mma_gemm<<<gemm_blocks, 256>>>(bufB, DD, DD, agg, RR * DD, cnt,
                                   blob + BLOB_COMB, 3 * DD, rgcn_b, bufA, M, 0);

    // conv2: bufA -> bufB
    zero_kernel<<<1184, 256>>>((float4*)agg, (float4*)cnt);
    edge_agg<<<edge_blocks, 128>>>(src, dst, etype, bufA, agg, cnt);
    mma_gemm<<<gemm_blocks, 256>>>(bufA, DD, DD, agg, RR * DD, cnt,
                                   blob + BLOB_COMB, 3 * DD, rgcn_b, bufB, M, 0);

    // out1 = lrelu(x @ W_out1 + b)
    mma_gemm<<<gemm_blocks, 256>>>(bufB, DD, DD, nullptr, 0, nullptr,
                                   blob + BLOB_WOUT1, DD, b_out1, bufA, M, 1);
    // out = out1 @ W_out2 + b2
    out2_kernel<<<(M + 3) / 4, 128>>>(bufA, W_out2, b_out2, out, M);
}

// round 7
// speedup vs baseline: 1.5535x; 1.4117x over previous
#include <cuda_runtime.h>
#include <cuda_fp16.h>
#include <cstdint>

#define N_NODES 100000
#define N_EDGES 600000
#define DD 128
#define TWD 768
#define RR 2

// ---------------------------------------------------------------------------
// Scratch (device globals — no allocation allowed)
// ---------------------------------------------------------------------------
__device__ float g_bufA[(size_t)N_NODES * DD];          // 51.2 MB
__device__ float g_bufB[(size_t)N_NODES * DD];          // 51.2 MB
__device__ float g_agg[(size_t)N_NODES * RR * DD];      // 102.4 MB
__device__ float g_cnt[(size_t)N_NODES * RR];           // 0.8 MB

// Weight fragment blobs (fp16): per stage, hi plane then lo plane.
// Plane layout: uint2 per (k16-step s, n8-tile j, lane): idx = ((s*16+j)*32+lane)
#define BLOB_TWEET 0
#define BLOB_WIN   196608
#define BLOB_COMB  229376
#define BLOB_WOUT1 327680
#define BLOB_TOTAL 360448
__device__ __half g_wblob[BLOB_TOTAL];

// ---------------------------------------------------------------------------
// MMA helpers (plain PTX: valid on sm_103 virtual target)
// ---------------------------------------------------------------------------
__device__ __forceinline__ void mma16816(float* c, const uint32_t* a, uint2 b) {
    asm volatile(
        "mma.sync.aligned.m16n8k16.row.col.f32.f16.f16.f32 "
        "{%0,%1,%2,%3}, {%4,%5,%6,%7}, {%8,%9}, {%0,%1,%2,%3};"
        : "+f"(c[0]), "+f"(c[1]), "+f"(c[2]), "+f"(c[3])
        : "r"(a[0]), "r"(a[1]), "r"(a[2]), "r"(a[3]), "r"(b.x), "r"(b.y));
}

__device__ __forceinline__ void ldmat4(uint32_t* d, uint32_t addr) {
    asm volatile("ldmatrix.sync.aligned.m8n8.x4.shared.b16 {%0,%1,%2,%3}, [%4];"
                 : "=r"(d[0]), "=r"(d[1]), "=r"(d[2]), "=r"(d[3]) : "r"(addr));
}

// fragment index (fp16 elems within a plane) for element (k, n)
__device__ __forceinline__ int frag_idx(int k, int n) {
    int s = k >> 4, j = n >> 3;
    int lane = (n & 7) * 4 + ((k & 7) >> 1);
    return ((((s * 16 + j) * 32 + lane) * 2 + ((k >> 3) & 1)) << 1) + (k & 1);
}

// ---------------------------------------------------------------------------
// Weight prep: fp32 W[K,128] -> fp16 hi/lo fragment planes
// ---------------------------------------------------------------------------
__global__ void convert_weights(
    const float* __restrict__ Wt, const float* __restrict__ Wi,
    const float* __restrict__ root, const float* __restrict__ rw,
    const float* __restrict__ Wo1, __half* __restrict__ blob)
{
    int i = blockIdx.x * blockDim.x + threadIdx.x;
    if (i >= 1408 * 128) return;
    int n = i & 127;
    int kk = i >> 7;
    float w; int k, base, Kphys;
    if (kk < 768)       { k = kk;        base = BLOB_TWEET; Kphys = 768; w = Wt[k * 128 + n]; }
    else if (kk < 896)  { k = kk - 768;  base = BLOB_WIN;   Kphys = 128; w = Wi[k * 128 + n]; }
    else if (kk < 1280) { k = kk - 896;  base = BLOB_COMB;  Kphys = 384;
                          w = (k < 128) ? root[k * 128 + n] : rw[(size_t)(k - 128) * 128 + n]; }
    else                { k = kk - 1280; base = BLOB_WOUT1; Kphys = 128; w = Wo1[k * 128 + n]; }

    __half h = __float2half_rn(w);
    __half l = __float2half_rn(w - __half2float(h));
    int fi = frag_idx(k, n);
    blob[base + fi] = h;
    blob[base + Kphys * 128 + fi] = l;
}

// ---------------------------------------------------------------------------
// HMMA GEMM, software-pipelined:
// C[M,128] = act( concat(A1[,:K1], A2_scaled)[M,Kphys] @ W + bias )
// A: single fp16 plane (double-buffered SMEM). B: pre-converted hi+lo planes.
// C = A*Bh + A*Bl  (B exact to ~2^-22; error = A fp16 rounding ~3e-4/stage)
// ---------------------------------------------------------------------------
__global__ __launch_bounds__(256, 2) void mma_gemm(
    const float* __restrict__ A1, int K1, int s1,
    const float* __restrict__ A2, int s2, const float* __restrict__ cnt,
    const __half* __restrict__ Wblob, int Kphys,
    const float* __restrict__ bias, float* __restrict__ C,
    int M, int act)
{
    __shared__ __half Ah[2][128][40];

    const int tid = threadIdx.x;
    const int wid = tid >> 5;
    const int lane = tid & 31;
    const int wr = wid & 3;           // 32-row group
    const int wc = wid >> 2;          // 64-col group
    const int row0 = blockIdx.x * 128;

    const uint2* __restrict__ BH = (const uint2*)Wblob;
    const uint2* __restrict__ BL = (const uint2*)(Wblob + (size_t)Kphys * 128);

    float acc[2][8][4];
#pragma unroll
    for (int mt = 0; mt < 2; mt++)
#pragma unroll
        for (int j = 0; j < 8; j++)
#pragma unroll
            for (int q = 0; q < 4; q++) acc[mt][j][q] = 0.f;

    // A-load assignment: 2 threads per row, 16 k each
    const int lrow = tid >> 1;
    const int lk = (tid & 1) * 16;
    const int gr = row0 + lrow;
    const bool av = gr < M;
    const uint32_t ah_base = (uint32_t)__cvta_generic_to_shared(&Ah[0][0][0]);
    const uint32_t bufstride = 128 * 40 * 2;

    float f[16];

    auto ldgA = [&](int c) {
        int kp = (c << 5) + lk;
#pragma unroll
        for (int i = 0; i < 16; i++) f[i] = 0.f;
        if (av) {
            const float* src;
            float sc = 1.f;
            if (kp < K1) {
                src = A1 + (size_t)gr * s1 + kp;
            } else {
                int ka = kp - K1;
                int rel = ka >> 7;
                sc = 1.f / fmaxf(__ldg(&cnt[gr * 2 + rel]), 1.f);
                src = A2 + (size_t)gr * s2 + ka;
            }
            float4 f0 = *(const float4*)(src + 0);
            float4 f1 = *(const float4*)(src + 4);
            float4 f2 = *(const float4*)(src + 8);
            float4 f3 = *(const float4*)(src + 12);
            f[0] = f0.x * sc; f[1] = f0.y * sc; f[2] = f0.z * sc; f[3] = f0.w * sc;
            f[4] = f1.x * sc; f[5] = f1.y * sc; f[6] = f1.z * sc; f[7] = f1.w * sc;
            f[8] = f2.x * sc; f[9] = f2.y * sc; f[10] = f2.z * sc; f[11] = f2.w * sc;
            f[12] = f3.x * sc; f[13] = f3.y * sc; f[14] = f3.z * sc; f[15] = f3.w * sc;
        }
    };
    auto stsA = [&](int b) {
        uint32_t* dh = (uint32_t*)&Ah[b][lrow][lk];
#pragma unroll
        for (int i = 0; i < 8; i++) {
            __half2 h;
            h.x = __float2half_rn(f[2 * i]);
            h.y = __float2half_rn(f[2 * i + 1]);
            dh[i] = *(uint32_t*)&h;
        }
    };

    const int nChunks = Kphys >> 5;
    ldgA(0);
    stsA(0);
    __syncthreads();

    for (int c = 0; c < nChunks; c++) {
        const int cur = c & 1;
        const bool more = (c + 1) < nChunks;
        if (more) ldgA(c + 1);    // LDGs in flight during the MMAs below

#pragma unroll
        for (int s = 0; s < 2; s++) {
            const int sg = c * 2 + s;
            const uint2* bh = BH + ((size_t)sg * 16 + wc * 8) * 32 + lane;
            const uint2* bl = BL + ((size_t)sg * 16 + wc * 8) * 32 + lane;

            uint32_t af[2][4];
            const int mrow = lane & 15;
            const int mk = (s << 4) + ((lane >> 4) << 3);
#pragma unroll
            for (int mt = 0; mt < 2; mt++) {
                uint32_t off = cur * bufstride + (uint32_t)(((wr * 32 + mt * 16 + mrow) * 40 + mk) * 2);
                ldmat4(af[mt], ah_base + off);
            }
            uint2 vh[8];
#pragma unroll
            for (int j = 0; j < 8; j++) vh[j] = __ldg(&bh[j * 32]);
#pragma unroll
            for (int j = 0; j < 8; j++) {
                mma16816(acc[0][j], af[0], vh[j]);
                mma16816(acc[1][j], af[1], vh[j]);
            }
#pragma unroll
            for (int j = 0; j < 8; j++) vh[j] = __ldg(&bl[j * 32]);
#pragma unroll
            for (int j = 0; j < 8; j++) {
                mma16816(acc[0][j], af[0], vh[j]);
                mma16816(acc[1][j], af[1], vh[j]);
            }
        }

        if (more) stsA(cur ^ 1);
        __syncthreads();
    }

    // ---- epilogue: bias + act + store ----
#pragma unroll
    for (int mt = 0; mt < 2; mt++) {
#pragma unroll
        for (int j = 0; j < 8; j++) {
            int col = wc * 64 + j * 8 + (lane & 3) * 2;
            int r0 = row0 + wr * 32 + mt * 16 + (lane >> 2);
            float b0 = __ldg(&bias[col]), b1 = __ldg(&bias[col + 1]);
            float v0 = acc[mt][j][0] + b0, v1 = acc[mt][j][1] + b1;
            float v2 = acc[mt][j][2] + b0, v3 = acc[mt][j][3] + b1;
            if (act) {
                v0 = (v0 > 0.f) ? v0 : 0.01f * v0;
                v1 = (v1 > 0.f) ? v1 : 0.01f * v1;
                v2 = (v2 > 0.f) ? v2 : 0.01f * v2;
                v3 = (v3 > 0.f) ? v3 : 0.01f * v3;
            }
            if (r0 < M)     *(float2*)&C[(size_t)r0 * 128 + col]       = make_float2(v0, v1);
            if (r0 + 8 < M) *(float2*)&C[(size_t)(r0 + 8) * 128 + col] = make_float2(v2, v3);
        }
    }
}

// ---------------------------------------------------------------------------
// Edge path
// ---------------------------------------------------------------------------
__global__ void zero_kernel(float4* __restrict__ agg4, float4* __restrict__ cnt4)
{
    const int stride = gridDim.x * blockDim.x;
    const int tot_agg = N_NODES * RR * DD / 4;
    const int tot_cnt = N_NODES * RR / 4;
    const float4 z = make_float4(0.f, 0.f, 0.f, 0.f);
    for (int i = blockIdx.x * blockDim.x + threadIdx.x; i < tot_agg; i += stride)
        agg4[i] = z;
    for (int i = blockIdx.x * blockDim.x + threadIdx.x; i < tot_cnt; i += stride)
        cnt4[i] = z;
}

__global__ __launch_bounds__(128) void edge_agg(
    const int* __restrict__ src, const int* __restrict__ dst,
    const int* __restrict__ et, const float* __restrict__ x,
    float* __restrict__ agg, float* __restrict__ cnt)
{
    const int t = threadIdx.x;
    const int e0 = blockIdx.x * 4;
#pragma unroll
    for (int i = 0; i < 4; i++) {
        int e = e0 + i;
        if (e >= N_EDGES) return;
        int s = __ldg(&src[e]);
        int d = __ldg(&dst[e]);
        int r = __ldg(&et[e]);
        float v = __ldg(&x[(size_t)s * 128 + t]);
        atomicAdd(&agg[((size_t)d * RR + r) * 128 + t], v);
        if (t == 0) atomicAdd(&cnt[(size_t)d * RR + r], 1.0f);
    }
}

__global__ __launch_bounds__(128) void out2_kernel(
    const float* __restrict__ x, const float* __restrict__ W,
    const float* __restrict__ b, float* __restrict__ out, int M)
{
    __shared__ float Ws[256];
    int tid = threadIdx.x;
    Ws[tid] = W[tid];
    Ws[tid + 128] = W[tid + 128];
    __syncthreads();

    int warp = tid >> 5, lane = tid & 31;
    int n = blockIdx.x * 4 + warp;
    if (n >= M) return;

    float4 v = *(const float4*)&x[(size_t)n * 128 + lane * 4];
    int k = lane * 4;
    float d0 = v.x * Ws[(k + 0) * 2] + v.y * Ws[(k + 1) * 2] +
               v.z * Ws[(k + 2) * 2] + v.w * Ws[(k + 3) * 2];
    float d1 = v.x * Ws[(k + 0) * 2 + 1] + v.y * Ws[(k + 1) * 2 + 1] +
               v.z * Ws[(k + 2) * 2 + 1] + v.w * Ws[(k + 3) * 2 + 1];
#pragma unroll
    for (int off = 16; off > 0; off >>= 1) {
        d0 += __shfl_down_sync(0xFFFFFFFFu, d0, off);
        d1 += __shfl_down_sync(0xFFFFFFFFu, d1, off);
    }
    if (lane == 0) {
        out[(size_t)n * 2 + 0] = d0 + b[0];
        out[(size_t)n * 2 + 1] = d1 + b[1];
    }
}

// ---------------------------------------------------------------------------
extern "C" void kernel_launch(void* const* d_in, const int* in_sizes, int n_in,
                              void* d_out, int out_size)
{
    const float* tweet     = (const float*)d_in[1];
    const int*   ei        = (const int*)d_in[4];
    const int*   etype     = (const int*)d_in[5];
    const float* W_tweet   = (const float*)d_in[6];
    const float* b_tweet   = (const float*)d_in[7];
    const float* W_in      = (const float*)d_in[8];
    const float* b_in      = (const float*)d_in[9];
    const float* rgcn_w    = (const float*)d_in[10];
    const float* rgcn_root = (const float*)d_in[11];
    const float* rgcn_b    = (const float*)d_in[12];
    const float* W_out1    = (const float*)d_in[13];
    const float* b_out1    = (const float*)d_in[14];
    const float* W_out2    = (const float*)d_in[15];
    const float* b_out2    = (const float*)d_in[16];
    float* out = (float*)d_out;

    float *bufA, *bufB, *agg, *cnt;
    __half* blob;
    cudaGetSymbolAddress((void**)&bufA, g_bufA);
    cudaGetSymbolAddress((void**)&bufB, g_bufB);
    cudaGetSymbolAddress((void**)&agg, g_agg);
    cudaGetSymbolAddress((void**)&cnt, g_cnt);
    cudaGetSymbolAddress((void**)&blob, g_wblob);

    const int M = N_NODES;
    const int gemm_blocks = (M + 127) / 128;
    const int edge_blocks = (N_EDGES + 3) / 4;

    const int* src = ei;
    const int* dst = ei + N_EDGES;

    convert_weights<<<(1408 * 128 + 255) / 256, 256>>>(W_tweet, W_in, rgcn_root, rgcn_w, W_out1, blob);

    // t = lrelu(tweet @ W_tweet + b)
    mma_gemm<<<gemm_blocks, 256>>>(tweet, TWD, TWD, nullptr, 0, nullptr,
                                   blob + BLOB_TWEET, TWD, b_tweet, bufA, M, 1);
    // x = lrelu(t @ W_in + b)
    mma_gemm<<<gemm_blocks, 256>>>(bufA, DD, DD, nullptr, 0, nullptr,
                                   blob + BLOB_WIN, DD, b_in, bufB, M, 1);

    // conv1: bufB -> bufA
    zero_kernel<<<1184, 256>>>((float4*)agg, (float4*)cnt);
    edge_agg<<<edge_blocks, 128>>>(src, dst, etype, bufB, agg, cnt);
    mma_gemm<<<gemm_blocks, 256>>>(bufB, DD, DD, agg, RR * DD, cnt,
                                   blob + BLOB_COMB, 3 * DD, rgcn_b, bufA, M, 0);

    // conv2: bufA -> bufB
    zero_kernel<<<1184, 256>>>((float4*)agg, (float4*)cnt);
    edge_agg<<<edge_blocks, 128>>>(src, dst, etype, bufA, agg, cnt);
    mma_gemm<<<gemm_blocks, 256>>>(bufA, DD, DD, agg, RR * DD, cnt,
                                   blob + BLOB_COMB, 3 * DD, rgcn_b, bufB, M, 0);

    // out1 = lrelu(x @ W_out1 + b)
    mma_gemm<<<gemm_blocks, 256>>>(bufB, DD, DD, nullptr, 0, nullptr,
                                   blob + BLOB_WOUT1, DD, b_out1, bufA, M, 1);
    // out = out1 @ W_out2 + b2
    out2_kernel<<<(M + 3) / 4, 128>>>(bufA, W_out2, b_out2, out, M);
}